// round 13
// baseline (speedup 1.0000x reference)
#include <cuda_runtime.h>
#include <cuda_fp16.h>

#define N_NODES 20000
#define F 256
#define R 32
#define NEI2 (R * R)
#define BN_EPS 1e-5f
#define FULLM 0xffffffffu

// ---------------- scratch (no allocations allowed) ----------------
__device__ float g_K[N_NODES];
__device__ float g_Q[N_NODES];
__device__ __align__(16) float g_QA[(size_t)N_NODES * R];    // Q[adj[c][j]] (NaN if masked)
__device__ __align__(16) unsigned short g_inh[(size_t)N_NODES * F];   // fp16 input copy
__device__ __align__(16) unsigned short g_aggh[(size_t)N_NODES * F];  // aggregated rows, fp16
__device__ __align__(16) unsigned short g_Wth[F * F];                 // W^T (n-major), fp16
__device__ float g_fin[(size_t)N_NODES * F];   // pre-BN final_h
__device__ float g_colsum[F];
__device__ float g_colsumsq[F];

__device__ __forceinline__ float nan_f()  { return __int_as_float(0x7fffffffu); }

// order-preserving float -> uint map (never 0 for non-NaN input)
__device__ __forceinline__ unsigned fmap(float v) {
    unsigned b = __float_as_uint(v);
    return (b & 0x80000000u) ? ~b : (b | 0x80000000u);
}

__device__ __forceinline__ void cp16(unsigned dst, const void* src, int sz) {
    asm volatile("cp.async.cg.shared.global [%0], [%1], 16, %2;"
                 :: "r"(dst), "l"(src), "r"(sz));
}

// ---------------- side stream + fork/join events (created pre-capture, no device mem APIs) ----
struct GraphStreams {
    cudaStream_t s2 = 0;
    cudaEvent_t e1 = 0, e2 = 0;
    bool ok = false;
    GraphStreams() {
        ok = (cudaStreamCreateWithFlags(&s2, cudaStreamNonBlocking) == cudaSuccess)
          && (cudaEventCreateWithFlags(&e1, cudaEventDisableTiming) == cudaSuccess)
          && (cudaEventCreateWithFlags(&e2, cudaEventDisableTiming) == cudaSuccess);
        if (!ok) s2 = 0;
    }
};
static GraphStreams g_gs;

// ---------------- kernel 1: Key/Query scalars + fp16 copy + BN-acc zeroing ----------------
__global__ void kq_kernel(const float* __restrict__ input,
                          const float* __restrict__ Wk,
                          const float* __restrict__ Wq) {
    if (blockIdx.x == 0) {
        int t = threadIdx.x;
        if (t < F) { g_colsum[t] = 0.0f; g_colsumsq[t] = 0.0f; }
    }
    int warp = (blockIdx.x * blockDim.x + threadIdx.x) >> 5;
    int lane = threadIdx.x & 31;
    if (warp >= N_NODES) return;
    const float4* row = (const float4*)(input + (size_t)warp * F);
    const float4* wk4 = (const float4*)Wk;
    const float4* wq4 = (const float4*)Wq;
    float4 x0 = row[lane];
    float4 x1 = row[32 + lane];
    float sk, sq;
    {
        float4 a = wk4[lane], a1 = wk4[32 + lane];
        sk = x0.x * a.x + x0.y * a.y + x0.z * a.z + x0.w * a.w
           + x1.x * a1.x + x1.y * a1.y + x1.z * a1.z + x1.w * a1.w;
        float4 b = wq4[lane], b1 = wq4[32 + lane];
        sq = x0.x * b.x + x0.y * b.y + x0.z * b.z + x0.w * b.w
           + x1.x * b1.x + x1.y * b1.y + x1.z * b1.z + x1.w * b1.w;
    }
    {
        __half2 h0 = __float22half2_rn(make_float2(x0.x, x0.y));
        __half2 h1 = __float22half2_rn(make_float2(x0.z, x0.w));
        __half2 h2 = __float22half2_rn(make_float2(x1.x, x1.y));
        __half2 h3 = __float22half2_rn(make_float2(x1.z, x1.w));
        uint2 p0 = make_uint2(*(unsigned*)&h0, *(unsigned*)&h1);
        uint2 p1 = make_uint2(*(unsigned*)&h2, *(unsigned*)&h3);
        *(uint2*)(g_inh + (size_t)warp * F + 4 * lane)       = p0;
        *(uint2*)(g_inh + (size_t)warp * F + 128 + 4 * lane) = p1;
    }
#pragma unroll
    for (int o = 16; o; o >>= 1) {
        sk += __shfl_xor_sync(FULLM, sk, o);
        sq += __shfl_xor_sync(FULLM, sq, o);
    }
    if (lane == 0) { g_K[warp] = sk; g_Q[warp] = sq; }
}

// ---------------- kernel 1b: QA table + W^T fp16 conversion + rf copy ----------------
__global__ void qa_kernel(const int* __restrict__ adj,
                          const float* __restrict__ W,
                          const int* __restrict__ rf,
                          float* __restrict__ out_rf) {
    int idx = blockIdx.x * blockDim.x + threadIdx.x;
    if (idx < F * F) {
        int n = idx >> 8, k = idx & (F - 1);
        g_Wth[idx] = __half_as_ushort(__float2half_rn(W[k * F + n]));
    }
    if (idx >= N_NODES * R) return;
    int id = adj[idx];
    g_QA[idx] = (id == N_NODES - 1) ? nan_f() : g_Q[id];
    if (out_rf) out_rf[idx] = (float)rf[idx];
}

// ---------------- kernel 2: attention softmax + fp16 aggregation (branchless inner loop) ----
__global__ void agg_kernel(const float* __restrict__ input,
                           const int* __restrict__ rf) {
    int gw = (blockIdx.x * blockDim.x + threadIdx.x) >> 5;
    int lane = threadIdx.x & 31;
    if (gw >= N_NODES) return;

    int rid = rf[gw * R + lane];
    float v = (rid == N_NODES - 1) ? -3.0e38f : g_K[gw] * g_Q[rid];
    float m = v;
#pragma unroll
    for (int o = 16; o; o >>= 1) m = fmaxf(m, __shfl_xor_sync(FULLM, m, o));
    float e = expf(v - m);   // masked: exactly 0.0f -> contributes nothing below
    float s = e;
#pragma unroll
    for (int o = 16; o; o >>= 1) s += __shfl_xor_sync(FULLM, s, o);
    float wgt = e / s;

    const float4* own = (const float4*)(input + (size_t)gw * F);
    float4 o0 = own[lane * 2];
    float4 o1 = own[lane * 2 + 1];
    float acc[8] = {o0.x, o0.y, o0.z, o0.w, o1.x, o1.y, o1.z, o1.w};

#pragma unroll 4
    for (int j = 0; j < R; j++) {
        float wj = __shfl_sync(FULLM, wgt, j);
        int id = __shfl_sync(FULLM, rid, j);
        uint4 h = *(const uint4*)(g_inh + (size_t)id * F + lane * 8);
        float2 f;
        f = __half22float2(*(__half2*)&h.x); acc[0] += wj * f.x; acc[1] += wj * f.y;
        f = __half22float2(*(__half2*)&h.y); acc[2] += wj * f.x; acc[3] += wj * f.y;
        f = __half22float2(*(__half2*)&h.z); acc[4] += wj * f.x; acc[5] += wj * f.y;
        f = __half22float2(*(__half2*)&h.w); acc[6] += wj * f.x; acc[7] += wj * f.y;
    }
    __half2 r0 = __float22half2_rn(make_float2(acc[0], acc[1]));
    __half2 r1 = __float22half2_rn(make_float2(acc[2], acc[3]));
    __half2 r2 = __float22half2_rn(make_float2(acc[4], acc[5]));
    __half2 r3 = __float22half2_rn(make_float2(acc[6], acc[7]));
    uint4 p = make_uint4(*(unsigned*)&r0, *(unsigned*)&r1, *(unsigned*)&r2, *(unsigned*)&r3);
    *(uint4*)(g_aggh + (size_t)gw * F + lane * 8) = p;
}

// ---------------- kernel 7: 2-hop expansion, exact stable top-32 of 1024 (R7-proven) ----------------
#define EWPB 8
#define VSTR 33
__global__ void expand_kernel(const int* __restrict__ rf,
                              const int* __restrict__ adj,
                              float* __restrict__ out_expand) {
    __shared__ unsigned V[EWPB][R * VSTR];
    int w = threadIdx.x >> 5;
    int lane = threadIdx.x & 31;
    int i = blockIdx.x * EWPB + w;
    if (i >= N_NODES) return;

    float key = g_K[i];
    int rfl = rf[i * R + lane];

    unsigned b0v = 0;
    int b0j = 0;
    const float4* qrow = (const float4*)(g_QA + (size_t)rfl * R);
    unsigned* Vrow = &V[w][lane * VSTR];
#pragma unroll
    for (int q = 0; q < 8; q++) {
        float4 x = qrow[q];
        float v0 = (x.x != x.x) ? -3.0e38f : key * x.x;
        float v1 = (x.y != x.y) ? -3.0e38f : key * x.y;
        float v2 = (x.z != x.z) ? -3.0e38f : key * x.z;
        float v3 = (x.w != x.w) ? -3.0e38f : key * x.w;
        unsigned m0 = fmap(v0), m1 = fmap(v1), m2 = fmap(v2), m3 = fmap(v3);
        Vrow[4 * q + 0] = m0;
        Vrow[4 * q + 1] = m1;
        Vrow[4 * q + 2] = m2;
        Vrow[4 * q + 3] = m3;
        if (m0 > b0v) { b0v = m0; b0j = 4 * q + 0; }
        if (m1 > b0v) { b0v = m1; b0j = 4 * q + 1; }
        if (m2 > b0v) { b0v = m2; b0j = 4 * q + 2; }
        if (m3 > b0v) { b0v = m3; b0j = 4 * q + 3; }
    }
    __syncwarp();

    int mwin = 0;
#pragma unroll 4
    for (int r = 0; r < R; r++) {
        unsigned mx = __reduce_max_sync(FULLM, b0v);
        unsigned cand = (b0v == mx) ? (unsigned)(lane * 32 + b0j) : FULLM;
        unsigned m = __reduce_min_sync(FULLM, cand);
        if (lane == r) mwin = (int)m;

        int winL = m >> 5, jwin = m & 31;
        unsigned x = V[w][winL * VSTR + lane];
        if (lane == jwin) {
            x = 0;
            V[w][winL * VSTR + jwin] = 0;
        }
        unsigned mx2 = __reduce_max_sync(FULLM, x);
        unsigned jc = (x == mx2) ? (unsigned)lane : FULLM;
        unsigned j2 = __reduce_min_sync(FULLM, jc);
        if (lane == winL) { b0v = mx2; b0j = (int)j2; }
        __syncwarp();
    }

    int k = mwin >> 5, j = mwin & 31;
    int rk = __shfl_sync(FULLM, rfl, k);
    out_expand[(size_t)i * R + lane] = (float)adj[(size_t)rk * R + j];
}

// ---------------- kernel 3: fp16 MMA GEMM (cp.async 2-stage, K-chunk 64) + fused col sums ----
#define GBM 128
#define GBN 128
#define GKC 64
#define ASTR 36                    // stride in half2 units
#define TSZ (GBM * ASTR)           // half2 per tile = 4608
#define STG (2 * TSZ)              // half2 per stage (A + B)
#define GEMM_SMEM (2 * STG * 4)    // bytes, 2 stages = 73728
#define NKT (F / GKC)              // 4

__global__ void __launch_bounds__(256, 2) gemm_kernel() {
    extern __shared__ unsigned sm[];           // half2 units
    unsigned smb = (unsigned)__cvta_generic_to_shared(sm);
    int bm = blockIdx.x * GBM;
    int bn = blockIdx.y * GBN;
    int t = threadIdx.x;
    int lane = t & 31, warp = t >> 5;
    int warp_m = warp >> 1, warp_n = warp & 1;
    int g = lane >> 2, tg = lane & 3;
    int m0 = warp_m * 32, n0 = warp_n * 64;

    int arow = t >> 1;
    int ah = (t & 1) * 32;
    int gr = bm + arow;
    int asz = (gr < N_NODES) ? 16 : 0;
    const unsigned short* asrc = g_aggh + (size_t)(gr < N_NODES ? gr : 0) * F + ah;
    const unsigned short* bsrc = g_Wth + (size_t)(bn + arow) * F + ah;

    float acc[2][8][4];
#pragma unroll
    for (int mt = 0; mt < 2; mt++)
#pragma unroll
        for (int nt = 0; nt < 8; nt++)
#pragma unroll
            for (int c = 0; c < 4; c++) acc[mt][nt][c] = 0.0f;

    auto issue = [&](int stage, int kt) {
        unsigned ab = smb + (stage * STG + arow * ASTR + (ah >> 1)) * 4;
        const unsigned short* as = asrc + kt;
#pragma unroll
        for (int q = 0; q < 4; q++) cp16(ab + q * 16, as + q * 8, asz);
        unsigned bb = smb + (stage * STG + TSZ + arow * ASTR + (ah >> 1)) * 4;
        const unsigned short* bs = bsrc + kt;
#pragma unroll
        for (int q = 0; q < 4; q++) cp16(bb + q * 16, bs + q * 8, 16);
        asm volatile("cp.async.commit_group;");
    };

    issue(0, 0);

    for (int s = 0; s < NKT; s++) {
        if (s + 1 < NKT) {
            issue((s + 1) & 1, (s + 1) * GKC);
            asm volatile("cp.async.wait_group 1;");
        } else {
            asm volatile("cp.async.wait_group 0;");
        }
        __syncthreads();

        const unsigned* As = sm + (s & 1) * STG;
        const unsigned* Bs = sm + (s & 1) * STG + TSZ;
#pragma unroll
        for (int kk = 0; kk < 4; kk++) {
            int k2 = kk * 8;
            unsigned af[2][4];
#pragma unroll
            for (int mt = 0; mt < 2; mt++) {
                int r0 = m0 + mt * 16 + g;
                af[mt][0] = As[r0 * ASTR + k2 + tg];
                af[mt][1] = As[(r0 + 8) * ASTR + k2 + tg];
                af[mt][2] = As[r0 * ASTR + k2 + tg + 4];
                af[mt][3] = As[(r0 + 8) * ASTR + k2 + tg + 4];
            }
            unsigned bf[8][2];
#pragma unroll
            for (int nt = 0; nt < 8; nt++) {
                int nr = n0 + nt * 8 + g;
                bf[nt][0] = Bs[nr * ASTR + k2 + tg];
                bf[nt][1] = Bs[nr * ASTR + k2 + tg + 4];
            }
#pragma unroll
            for (int mt = 0; mt < 2; mt++)
#pragma unroll
                for (int nt = 0; nt < 8; nt++) {
                    asm volatile(
                        "mma.sync.aligned.m16n8k16.row.col.f32.f16.f16.f32 "
                        "{%0,%1,%2,%3}, {%4,%5,%6,%7}, {%8,%9}, {%0,%1,%2,%3};"
                        : "+f"(acc[mt][nt][0]), "+f"(acc[mt][nt][1]),
                          "+f"(acc[mt][nt][2]), "+f"(acc[mt][nt][3])
                        : "r"(af[mt][0]), "r"(af[mt][1]), "r"(af[mt][2]), "r"(af[mt][3]),
                          "r"(bf[nt][0]), "r"(bf[nt][1]));
                }
        }
        __syncthreads();
    }

#pragma unroll
    for (int mt = 0; mt < 2; mt++) {
        int row0 = bm + m0 + mt * 16 + g;
        int row1 = row0 + 8;
#pragma unroll
        for (int nt = 0; nt < 8; nt++) {
            int col = bn + n0 + nt * 8 + 2 * tg;
            if (row0 < N_NODES)
                *(float2*)(g_fin + (size_t)row0 * F + col) =
                    make_float2(acc[mt][nt][0], acc[mt][nt][1]);
            if (row1 < N_NODES)
                *(float2*)(g_fin + (size_t)row1 * F + col) =
                    make_float2(acc[mt][nt][2], acc[mt][nt][3]);
        }
    }
#pragma unroll
    for (int nt = 0; nt < 8; nt++) {
        float s0 = acc[0][nt][0] + acc[0][nt][2] + acc[1][nt][0] + acc[1][nt][2];
        float s1 = acc[0][nt][1] + acc[0][nt][3] + acc[1][nt][1] + acc[1][nt][3];
        float q0 = acc[0][nt][0] * acc[0][nt][0] + acc[0][nt][2] * acc[0][nt][2]
                 + acc[1][nt][0] * acc[1][nt][0] + acc[1][nt][2] * acc[1][nt][2];
        float q1 = acc[0][nt][1] * acc[0][nt][1] + acc[0][nt][3] * acc[0][nt][3]
                 + acc[1][nt][1] * acc[1][nt][1] + acc[1][nt][3] * acc[1][nt][3];
#pragma unroll
        for (int o = 4; o <= 16; o <<= 1) {
            s0 += __shfl_xor_sync(FULLM, s0, o);
            s1 += __shfl_xor_sync(FULLM, s1, o);
            q0 += __shfl_xor_sync(FULLM, q0, o);
            q1 += __shfl_xor_sync(FULLM, q1, o);
        }
        if (lane < 4) {
            int col = bn + n0 + nt * 8 + 2 * tg;
            atomicAdd(&g_colsum[col], s0);
            atomicAdd(&g_colsum[col + 1], s1);
            atomicAdd(&g_colsumsq[col], q0);
            atomicAdd(&g_colsumsq[col + 1], q1);
        }
    }
}

// ---------------- kernel 5: batchnorm + relu -> out (2 x float4 per thread) ----------------
__global__ void bn_kernel(const float* __restrict__ gamma,
                          const float* __restrict__ beta,
                          float* __restrict__ out) {
    int idx8 = blockIdx.x * blockDim.x + threadIdx.x;
    if (idx8 >= N_NODES * F / 8) return;
    const float invn = 1.0f / (float)N_NODES;
    size_t base = (size_t)idx8 * 8;
    int c = (int)(base & (F - 1));
    float4 x0 = *(const float4*)(g_fin + base);
    float4 x1 = *(const float4*)(g_fin + base + 4);
    float4 y0, y1;
#pragma unroll
    for (int q = 0; q < 8; q++) {
        int cc = c + q;
        float mean = g_colsum[cc] * invn;
        float var = g_colsumsq[cc] * invn - mean * mean;
        float xx = (q < 4) ? ((const float*)&x0)[q] : ((const float*)&x1)[q - 4];
        float yy = fmaxf(gamma[cc] * (xx - mean) * rsqrtf(var + BN_EPS) + beta[cc], 0.0f);
        if (q < 4) ((float*)&y0)[q] = yy; else ((float*)&y1)[q - 4] = yy;
    }
    *(float4*)(out + base) = y0;
    *(float4*)(out + base + 4) = y1;
}

// ---------------- launch: parallel graph via event fork/join ----------------
extern "C" void kernel_launch(void* const* d_in, const int* in_sizes, int n_in,
                              void* d_out, int out_size) {
    const float* input = (const float*)d_in[0];
    const int*   rf    = (const int*)d_in[1];
    const int*   adj   = (const int*)d_in[2];
    const float* W     = (const float*)d_in[3];
    const float* Wk    = (const float*)d_in[4];
    const float* Wq    = (const float*)d_in[5];
    const float* gamma = (const float*)d_in[6];
    const float* beta  = (const float*)d_in[7];
    float* out = (float*)d_out;

    static bool attr_done = false;
    if (!attr_done) {
        cudaFuncSetAttribute(gemm_kernel,
                             cudaFuncAttributeMaxDynamicSharedMemorySize, GEMM_SMEM);
        attr_done = true;
    }

    bool full_out = (out_size >= N_NODES * F + 2 * N_NODES * R);
    float* out_rf = full_out ? (out + N_NODES * F) : nullptr;
    float* out_ex = full_out ? (out + N_NODES * F + N_NODES * R) : nullptr;
    bool fork = full_out && g_gs.ok;

    kq_kernel<<<(N_NODES * 32 + 255) / 256, 256>>>(input, Wk, Wq);
    qa_kernel<<<(N_NODES * R + 255) / 256, 256>>>(adj, W, rf, out_rf);

    if (full_out) {
        if (fork) {
            cudaEventRecord(g_gs.e1, 0);
            cudaStreamWaitEvent(g_gs.s2, g_gs.e1, 0);
            expand_kernel<<<(N_NODES + EWPB - 1) / EWPB, EWPB * 32, 0, g_gs.s2>>>(
                rf, adj, out_ex);
            cudaEventRecord(g_gs.e2, g_gs.s2);
        } else {
            expand_kernel<<<(N_NODES + EWPB - 1) / EWPB, EWPB * 32>>>(rf, adj, out_ex);
        }
    }

    agg_kernel<<<(N_NODES * 32 + 255) / 256, 256>>>(input, rf);
    dim3 gg((N_NODES + GBM - 1) / GBM, F / GBN);
    gemm_kernel<<<gg, 256, GEMM_SMEM>>>();

    if (fork) cudaStreamWaitEvent(0, g_gs.e2, 0);
    bn_kernel<<<(N_NODES * F / 8 + 255) / 256, 256>>>(gamma, beta, out);
}

// round 14
// speedup vs baseline: 1.0781x; 1.0781x over previous
#include <cuda_runtime.h>
#include <cuda_fp16.h>

#define N_NODES 20000
#define F 256
#define R 32
#define NEI2 (R * R)
#define BN_EPS 1e-5f
#define FULLM 0xffffffffu

// ---------------- scratch (no allocations allowed) ----------------
__device__ float g_K[N_NODES];
__device__ float g_Q[N_NODES];
__device__ __align__(16) float g_QA[(size_t)N_NODES * R];    // Q[adj[c][j]] (NaN if masked)
__device__ __align__(16) unsigned short g_inh[(size_t)N_NODES * F];   // fp16 input copy
__device__ __align__(16) unsigned short g_aggh[(size_t)N_NODES * F];  // aggregated rows, fp16
__device__ __align__(16) unsigned short g_Wth[F * F];                 // W^T (n-major), fp16
__device__ float g_fin[(size_t)N_NODES * F];   // pre-BN final_h
__device__ float g_colsum[F];
__device__ float g_colsumsq[F];

__device__ __forceinline__ float nan_f()  { return __int_as_float(0x7fffffffu); }

// order-preserving float -> uint map (never 0 for non-NaN input)
__device__ __forceinline__ unsigned fmap(float v) {
    unsigned b = __float_as_uint(v);
    return (b & 0x80000000u) ? ~b : (b | 0x80000000u);
}

__device__ __forceinline__ void cp16(unsigned dst, const void* src, int sz) {
    asm volatile("cp.async.cg.shared.global [%0], [%1], 16, %2;"
                 :: "r"(dst), "l"(src), "r"(sz));
}

// ---------------- side stream + fork/join events (created pre-capture, no device mem APIs) ----
struct GraphStreams {
    cudaStream_t s2 = 0;
    cudaEvent_t e1 = 0, e2 = 0;
    bool ok = false;
    GraphStreams() {
        ok = (cudaStreamCreateWithFlags(&s2, cudaStreamNonBlocking) == cudaSuccess)
          && (cudaEventCreateWithFlags(&e1, cudaEventDisableTiming) == cudaSuccess)
          && (cudaEventCreateWithFlags(&e2, cudaEventDisableTiming) == cudaSuccess);
        if (!ok) s2 = 0;
    }
};
static GraphStreams g_gs;

// ---------------- kernel 1: Key/Query scalars + fp16 copy + BN-acc zeroing ----------------
__global__ void kq_kernel(const float* __restrict__ input,
                          const float* __restrict__ Wk,
                          const float* __restrict__ Wq) {
    if (blockIdx.x == 0) {
        int t = threadIdx.x;
        if (t < F) { g_colsum[t] = 0.0f; g_colsumsq[t] = 0.0f; }
    }
    int warp = (blockIdx.x * blockDim.x + threadIdx.x) >> 5;
    int lane = threadIdx.x & 31;
    if (warp >= N_NODES) return;
    const float4* row = (const float4*)(input + (size_t)warp * F);
    const float4* wk4 = (const float4*)Wk;
    const float4* wq4 = (const float4*)Wq;
    float4 x0 = row[lane];
    float4 x1 = row[32 + lane];
    float sk, sq;
    {
        float4 a = wk4[lane], a1 = wk4[32 + lane];
        sk = x0.x * a.x + x0.y * a.y + x0.z * a.z + x0.w * a.w
           + x1.x * a1.x + x1.y * a1.y + x1.z * a1.z + x1.w * a1.w;
        float4 b = wq4[lane], b1 = wq4[32 + lane];
        sq = x0.x * b.x + x0.y * b.y + x0.z * b.z + x0.w * b.w
           + x1.x * b1.x + x1.y * b1.y + x1.z * b1.z + x1.w * b1.w;
    }
    {
        __half2 h0 = __float22half2_rn(make_float2(x0.x, x0.y));
        __half2 h1 = __float22half2_rn(make_float2(x0.z, x0.w));
        __half2 h2 = __float22half2_rn(make_float2(x1.x, x1.y));
        __half2 h3 = __float22half2_rn(make_float2(x1.z, x1.w));
        uint2 p0 = make_uint2(*(unsigned*)&h0, *(unsigned*)&h1);
        uint2 p1 = make_uint2(*(unsigned*)&h2, *(unsigned*)&h3);
        *(uint2*)(g_inh + (size_t)warp * F + 4 * lane)       = p0;
        *(uint2*)(g_inh + (size_t)warp * F + 128 + 4 * lane) = p1;
    }
#pragma unroll
    for (int o = 16; o; o >>= 1) {
        sk += __shfl_xor_sync(FULLM, sk, o);
        sq += __shfl_xor_sync(FULLM, sq, o);
    }
    if (lane == 0) { g_K[warp] = sk; g_Q[warp] = sq; }
}

// ---------------- kernel 1b: QA table + W^T fp16 conversion + rf copy ----------------
__global__ void qa_kernel(const int* __restrict__ adj,
                          const float* __restrict__ W,
                          const int* __restrict__ rf,
                          float* __restrict__ out_rf) {
    int idx = blockIdx.x * blockDim.x + threadIdx.x;
    if (idx < F * F) {
        int n = idx >> 8, k = idx & (F - 1);
        g_Wth[idx] = __half_as_ushort(__float2half_rn(W[k * F + n]));
    }
    if (idx >= N_NODES * R) return;
    int id = adj[idx];
    g_QA[idx] = (id == N_NODES - 1) ? nan_f() : g_Q[id];
    if (out_rf) out_rf[idx] = (float)rf[idx];
}

// ---------------- kernel 2: attention softmax + fp16 aggregation (branchless inner loop) ----
__global__ void agg_kernel(const float* __restrict__ input,
                           const int* __restrict__ rf) {
    int gw = (blockIdx.x * blockDim.x + threadIdx.x) >> 5;
    int lane = threadIdx.x & 31;
    if (gw >= N_NODES) return;

    int rid = rf[gw * R + lane];
    float v = (rid == N_NODES - 1) ? -3.0e38f : g_K[gw] * g_Q[rid];
    float m = v;
#pragma unroll
    for (int o = 16; o; o >>= 1) m = fmaxf(m, __shfl_xor_sync(FULLM, m, o));
    float e = expf(v - m);   // masked: exactly 0.0f -> contributes nothing below
    float s = e;
#pragma unroll
    for (int o = 16; o; o >>= 1) s += __shfl_xor_sync(FULLM, s, o);
    float wgt = e / s;

    const float4* own = (const float4*)(input + (size_t)gw * F);
    float4 o0 = own[lane * 2];
    float4 o1 = own[lane * 2 + 1];
    float acc[8] = {o0.x, o0.y, o0.z, o0.w, o1.x, o1.y, o1.z, o1.w};

#pragma unroll 4
    for (int j = 0; j < R; j++) {
        float wj = __shfl_sync(FULLM, wgt, j);
        int id = __shfl_sync(FULLM, rid, j);
        uint4 h = *(const uint4*)(g_inh + (size_t)id * F + lane * 8);
        float2 f;
        f = __half22float2(*(__half2*)&h.x); acc[0] += wj * f.x; acc[1] += wj * f.y;
        f = __half22float2(*(__half2*)&h.y); acc[2] += wj * f.x; acc[3] += wj * f.y;
        f = __half22float2(*(__half2*)&h.z); acc[4] += wj * f.x; acc[5] += wj * f.y;
        f = __half22float2(*(__half2*)&h.w); acc[6] += wj * f.x; acc[7] += wj * f.y;
    }
    __half2 r0 = __float22half2_rn(make_float2(acc[0], acc[1]));
    __half2 r1 = __float22half2_rn(make_float2(acc[2], acc[3]));
    __half2 r2 = __float22half2_rn(make_float2(acc[4], acc[5]));
    __half2 r3 = __float22half2_rn(make_float2(acc[6], acc[7]));
    uint4 p = make_uint4(*(unsigned*)&r0, *(unsigned*)&r1, *(unsigned*)&r2, *(unsigned*)&r3);
    *(uint4*)(g_aggh + (size_t)gw * F + lane * 8) = p;
}

// ---------------- kernel 7: 2-hop expansion, exact stable top-32 of 1024 (R7-proven) ----------------
#define EWPB 8
#define VSTR 33
__global__ void expand_kernel(const int* __restrict__ rf,
                              const int* __restrict__ adj,
                              float* __restrict__ out_expand) {
    __shared__ unsigned V[EWPB][R * VSTR];
    int w = threadIdx.x >> 5;
    int lane = threadIdx.x & 31;
    int i = blockIdx.x * EWPB + w;
    if (i >= N_NODES) return;

    float key = g_K[i];
    int rfl = rf[i * R + lane];

    unsigned b0v = 0;
    int b0j = 0;
    const float4* qrow = (const float4*)(g_QA + (size_t)rfl * R);
    unsigned* Vrow = &V[w][lane * VSTR];
#pragma unroll
    for (int q = 0; q < 8; q++) {
        float4 x = qrow[q];
        float v0 = (x.x != x.x) ? -3.0e38f : key * x.x;
        float v1 = (x.y != x.y) ? -3.0e38f : key * x.y;
        float v2 = (x.z != x.z) ? -3.0e38f : key * x.z;
        float v3 = (x.w != x.w) ? -3.0e38f : key * x.w;
        unsigned m0 = fmap(v0), m1 = fmap(v1), m2 = fmap(v2), m3 = fmap(v3);
        Vrow[4 * q + 0] = m0;
        Vrow[4 * q + 1] = m1;
        Vrow[4 * q + 2] = m2;
        Vrow[4 * q + 3] = m3;
        if (m0 > b0v) { b0v = m0; b0j = 4 * q + 0; }
        if (m1 > b0v) { b0v = m1; b0j = 4 * q + 1; }
        if (m2 > b0v) { b0v = m2; b0j = 4 * q + 2; }
        if (m3 > b0v) { b0v = m3; b0j = 4 * q + 3; }
    }
    __syncwarp();

    int mwin = 0;
#pragma unroll 4
    for (int r = 0; r < R; r++) {
        unsigned mx = __reduce_max_sync(FULLM, b0v);
        unsigned cand = (b0v == mx) ? (unsigned)(lane * 32 + b0j) : FULLM;
        unsigned m = __reduce_min_sync(FULLM, cand);
        if (lane == r) mwin = (int)m;

        int winL = m >> 5, jwin = m & 31;
        unsigned x = V[w][winL * VSTR + lane];
        if (lane == jwin) {
            x = 0;
            V[w][winL * VSTR + jwin] = 0;
        }
        unsigned mx2 = __reduce_max_sync(FULLM, x);
        unsigned jc = (x == mx2) ? (unsigned)lane : FULLM;
        unsigned j2 = __reduce_min_sync(FULLM, jc);
        if (lane == winL) { b0v = mx2; b0j = (int)j2; }
        __syncwarp();
    }

    int k = mwin >> 5, j = mwin & 31;
    int rk = __shfl_sync(FULLM, rfl, k);
    out_expand[(size_t)i * R + lane] = (float)adj[(size_t)rk * R + j];
}

// ---------------- kernel 3: fp16 MMA GEMM (cp.async 2-stage, K-chunk 64) + fused col sums ----
#define GBM 128
#define GBN 128
#define GKC 64
#define ASTR 36                    // stride in half2 units
#define TSZ (GBM * ASTR)           // half2 per tile = 4608
#define STG (2 * TSZ)              // half2 per stage (A + B)
#define GEMM_SMEM (2 * STG * 4)    // bytes, 2 stages = 73728
#define NKT (F / GKC)              // 4

__global__ void __launch_bounds__(256, 2) gemm_kernel() {
    extern __shared__ unsigned sm[];           // half2 units
    unsigned smb = (unsigned)__cvta_generic_to_shared(sm);
    int bm = blockIdx.x * GBM;
    int bn = blockIdx.y * GBN;
    int t = threadIdx.x;
    int lane = t & 31, warp = t >> 5;
    int warp_m = warp >> 1, warp_n = warp & 1;
    int g = lane >> 2, tg = lane & 3;
    int m0 = warp_m * 32, n0 = warp_n * 64;

    int arow = t >> 1;
    int ah = (t & 1) * 32;
    int gr = bm + arow;
    int asz = (gr < N_NODES) ? 16 : 0;
    const unsigned short* asrc = g_aggh + (size_t)(gr < N_NODES ? gr : 0) * F + ah;
    const unsigned short* bsrc = g_Wth + (size_t)(bn + arow) * F + ah;

    float acc[2][8][4];
#pragma unroll
    for (int mt = 0; mt < 2; mt++)
#pragma unroll
        for (int nt = 0; nt < 8; nt++)
#pragma unroll
            for (int c = 0; c < 4; c++) acc[mt][nt][c] = 0.0f;

    auto issue = [&](int stage, int kt) {
        unsigned ab = smb + (stage * STG + arow * ASTR + (ah >> 1)) * 4;
        const unsigned short* as = asrc + kt;
#pragma unroll
        for (int q = 0; q < 4; q++) cp16(ab + q * 16, as + q * 8, asz);
        unsigned bb = smb + (stage * STG + TSZ + arow * ASTR + (ah >> 1)) * 4;
        const unsigned short* bs = bsrc + kt;
#pragma unroll
        for (int q = 0; q < 4; q++) cp16(bb + q * 16, bs + q * 8, 16);
        asm volatile("cp.async.commit_group;");
    };

    issue(0, 0);

    for (int s = 0; s < NKT; s++) {
        if (s + 1 < NKT) {
            issue((s + 1) & 1, (s + 1) * GKC);
            asm volatile("cp.async.wait_group 1;");
        } else {
            asm volatile("cp.async.wait_group 0;");
        }
        __syncthreads();

        const unsigned* As = sm + (s & 1) * STG;
        const unsigned* Bs = sm + (s & 1) * STG + TSZ;
#pragma unroll
        for (int kk = 0; kk < 4; kk++) {
            int k2 = kk * 8;
            unsigned af[2][4];
#pragma unroll
            for (int mt = 0; mt < 2; mt++) {
                int r0 = m0 + mt * 16 + g;
                af[mt][0] = As[r0 * ASTR + k2 + tg];
                af[mt][1] = As[(r0 + 8) * ASTR + k2 + tg];
                af[mt][2] = As[r0 * ASTR + k2 + tg + 4];
                af[mt][3] = As[(r0 + 8) * ASTR + k2 + tg + 4];
            }
            unsigned bf[8][2];
#pragma unroll
            for (int nt = 0; nt < 8; nt++) {
                int nr = n0 + nt * 8 + g;
                bf[nt][0] = Bs[nr * ASTR + k2 + tg];
                bf[nt][1] = Bs[nr * ASTR + k2 + tg + 4];
            }
#pragma unroll
            for (int mt = 0; mt < 2; mt++)
#pragma unroll
                for (int nt = 0; nt < 8; nt++) {
                    asm volatile(
                        "mma.sync.aligned.m16n8k16.row.col.f32.f16.f16.f32 "
                        "{%0,%1,%2,%3}, {%4,%5,%6,%7}, {%8,%9}, {%0,%1,%2,%3};"
                        : "+f"(acc[mt][nt][0]), "+f"(acc[mt][nt][1]),
                          "+f"(acc[mt][nt][2]), "+f"(acc[mt][nt][3])
                        : "r"(af[mt][0]), "r"(af[mt][1]), "r"(af[mt][2]), "r"(af[mt][3]),
                          "r"(bf[nt][0]), "r"(bf[nt][1]));
                }
        }
        __syncthreads();
    }

#pragma unroll
    for (int mt = 0; mt < 2; mt++) {
        int row0 = bm + m0 + mt * 16 + g;
        int row1 = row0 + 8;
#pragma unroll
        for (int nt = 0; nt < 8; nt++) {
            int col = bn + n0 + nt * 8 + 2 * tg;
            if (row0 < N_NODES)
                *(float2*)(g_fin + (size_t)row0 * F + col) =
                    make_float2(acc[mt][nt][0], acc[mt][nt][1]);
            if (row1 < N_NODES)
                *(float2*)(g_fin + (size_t)row1 * F + col) =
                    make_float2(acc[mt][nt][2], acc[mt][nt][3]);
        }
    }
#pragma unroll
    for (int nt = 0; nt < 8; nt++) {
        float s0 = acc[0][nt][0] + acc[0][nt][2] + acc[1][nt][0] + acc[1][nt][2];
        float s1 = acc[0][nt][1] + acc[0][nt][3] + acc[1][nt][1] + acc[1][nt][3];
        float q0 = acc[0][nt][0] * acc[0][nt][0] + acc[0][nt][2] * acc[0][nt][2]
                 + acc[1][nt][0] * acc[1][nt][0] + acc[1][nt][2] * acc[1][nt][2];
        float q1 = acc[0][nt][1] * acc[0][nt][1] + acc[0][nt][3] * acc[0][nt][3]
                 + acc[1][nt][1] * acc[1][nt][1] + acc[1][nt][3] * acc[1][nt][3];
#pragma unroll
        for (int o = 4; o <= 16; o <<= 1) {
            s0 += __shfl_xor_sync(FULLM, s0, o);
            s1 += __shfl_xor_sync(FULLM, s1, o);
            q0 += __shfl_xor_sync(FULLM, q0, o);
            q1 += __shfl_xor_sync(FULLM, q1, o);
        }
        if (lane < 4) {
            int col = bn + n0 + nt * 8 + 2 * tg;
            atomicAdd(&g_colsum[col], s0);
            atomicAdd(&g_colsum[col + 1], s1);
            atomicAdd(&g_colsumsq[col], q0);
            atomicAdd(&g_colsumsq[col + 1], q1);
        }
    }
}

// ---------------- kernel 5: batchnorm + relu -> out (float4 per thread, R12-proven) ----------
__global__ void bn_kernel(const float* __restrict__ gamma,
                          const float* __restrict__ beta,
                          float* __restrict__ out) {
    int idx4 = blockIdx.x * blockDim.x + threadIdx.x;
    if (idx4 >= N_NODES * F / 4) return;
    int c = (idx4 * 4) & (F - 1);
    const float invn = 1.0f / (float)N_NODES;
    float4 x = *(const float4*)(g_fin + (size_t)idx4 * 4);
    float4 y;
    {
        float mean = g_colsum[c + 0] * invn;
        float var = g_colsumsq[c + 0] * invn - mean * mean;
        y.x = fmaxf(gamma[c + 0] * (x.x - mean) * rsqrtf(var + BN_EPS) + beta[c + 0], 0.0f);
    }
    {
        float mean = g_colsum[c + 1] * invn;
        float var = g_colsumsq[c + 1] * invn - mean * mean;
        y.y = fmaxf(gamma[c + 1] * (x.y - mean) * rsqrtf(var + BN_EPS) + beta[c + 1], 0.0f);
    }
    {
        float mean = g_colsum[c + 2] * invn;
        float var = g_colsumsq[c + 2] * invn - mean * mean;
        y.z = fmaxf(gamma[c + 2] * (x.z - mean) * rsqrtf(var + BN_EPS) + beta[c + 2], 0.0f);
    }
    {
        float mean = g_colsum[c + 3] * invn;
        float var = g_colsumsq[c + 3] * invn - mean * mean;
        y.w = fmaxf(gamma[c + 3] * (x.w - mean) * rsqrtf(var + BN_EPS) + beta[c + 3], 0.0f);
    }
    *(float4*)(out + (size_t)idx4 * 4) = y;
}

// ---------------- launch: parallel graph via event fork/join ----------------
extern "C" void kernel_launch(void* const* d_in, const int* in_sizes, int n_in,
                              void* d_out, int out_size) {
    const float* input = (const float*)d_in[0];
    const int*   rf    = (const int*)d_in[1];
    const int*   adj   = (const int*)d_in[2];
    const float* W     = (const float*)d_in[3];
    const float* Wk    = (const float*)d_in[4];
    const float* Wq    = (const float*)d_in[5];
    const float* gamma = (const float*)d_in[6];
    const float* beta  = (const float*)d_in[7];
    float* out = (float*)d_out;

    static bool attr_done = false;
    if (!attr_done) {
        cudaFuncSetAttribute(gemm_kernel,
                             cudaFuncAttributeMaxDynamicSharedMemorySize, GEMM_SMEM);
        attr_done = true;
    }

    bool full_out = (out_size >= N_NODES * F + 2 * N_NODES * R);
    float* out_rf = full_out ? (out + N_NODES * F) : nullptr;
    float* out_ex = full_out ? (out + N_NODES * F + N_NODES * R) : nullptr;
    bool fork = full_out && g_gs.ok;

    kq_kernel<<<(N_NODES * 32 + 255) / 256, 256>>>(input, Wk, Wq);
    qa_kernel<<<(N_NODES * R + 255) / 256, 256>>>(adj, W, rf, out_rf);

    if (full_out) {
        if (fork) {
            cudaEventRecord(g_gs.e1, 0);
            cudaStreamWaitEvent(g_gs.s2, g_gs.e1, 0);
            expand_kernel<<<(N_NODES + EWPB - 1) / EWPB, EWPB * 32, 0, g_gs.s2>>>(
                rf, adj, out_ex);
            cudaEventRecord(g_gs.e2, g_gs.s2);
        } else {
            expand_kernel<<<(N_NODES + EWPB - 1) / EWPB, EWPB * 32>>>(rf, adj, out_ex);
        }
    }

    agg_kernel<<<(N_NODES * 32 + 255) / 256, 256>>>(input, rf);
    dim3 gg((N_NODES + GBM - 1) / GBM, F / GBN);
    gemm_kernel<<<gg, 256, GEMM_SMEM>>>();

    if (fork) cudaStreamWaitEvent(0, g_gs.e2, 0);
    bn_kernel<<<(N_NODES * F / 4 + 255) / 256, 256>>>(gamma, beta, out);
}

// round 15
// speedup vs baseline: 1.1797x; 1.0942x over previous
#include <cuda_runtime.h>
#include <cuda_fp16.h>

#define N_NODES 20000
#define F 256
#define R 32
#define NEI2 (R * R)
#define BN_EPS 1e-5f
#define FULLM 0xffffffffu

// ---------------- scratch (no allocations allowed) ----------------
__device__ float g_K[N_NODES];
__device__ float g_Q[N_NODES];
__device__ __align__(16) float g_QA[(size_t)N_NODES * R];    // Q[adj[c][j]] (NaN if masked)
__device__ __align__(16) unsigned short g_inh[(size_t)N_NODES * F];   // fp16 input copy
__device__ __align__(16) unsigned short g_aggh[(size_t)N_NODES * F];  // aggregated rows, fp16
__device__ __align__(16) unsigned short g_Wth[F * F];                 // W^T (n-major), fp16
__device__ float g_fin[(size_t)N_NODES * F];   // pre-BN final_h
__device__ float g_colsum[F];
__device__ float g_colsumsq[F];

__device__ __forceinline__ float nan_f()  { return __int_as_float(0x7fffffffu); }

// order-preserving float -> uint map (never 0 for non-NaN input)
__device__ __forceinline__ unsigned fmap(float v) {
    unsigned b = __float_as_uint(v);
    return (b & 0x80000000u) ? ~b : (b | 0x80000000u);
}

__device__ __forceinline__ void cp16(unsigned dst, const void* src, int sz) {
    asm volatile("cp.async.cg.shared.global [%0], [%1], 16, %2;"
                 :: "r"(dst), "l"(src), "r"(sz));
}

// ---------------- side stream + fork/join events (created pre-capture, no device mem APIs) ----
struct GraphStreams {
    cudaStream_t s2 = 0;
    cudaEvent_t e1 = 0, eqa = 0, e2 = 0;
    bool ok = false;
    GraphStreams() {
        ok = (cudaStreamCreateWithFlags(&s2, cudaStreamNonBlocking) == cudaSuccess)
          && (cudaEventCreateWithFlags(&e1, cudaEventDisableTiming) == cudaSuccess)
          && (cudaEventCreateWithFlags(&eqa, cudaEventDisableTiming) == cudaSuccess)
          && (cudaEventCreateWithFlags(&e2, cudaEventDisableTiming) == cudaSuccess);
        if (!ok) s2 = 0;
    }
};
static GraphStreams g_gs;

// ---------------- kernel 1: Key/Query scalars + fp16 copy + BN-acc zeroing ----------------
__global__ void kq_kernel(const float* __restrict__ input,
                          const float* __restrict__ Wk,
                          const float* __restrict__ Wq) {
    if (blockIdx.x == 0) {
        int t = threadIdx.x;
        if (t < F) { g_colsum[t] = 0.0f; g_colsumsq[t] = 0.0f; }
    }
    int warp = (blockIdx.x * blockDim.x + threadIdx.x) >> 5;
    int lane = threadIdx.x & 31;
    if (warp >= N_NODES) return;
    const float4* row = (const float4*)(input + (size_t)warp * F);
    const float4* wk4 = (const float4*)Wk;
    const float4* wq4 = (const float4*)Wq;
    float4 x0 = row[lane];
    float4 x1 = row[32 + lane];
    float sk, sq;
    {
        float4 a = wk4[lane], a1 = wk4[32 + lane];
        sk = x0.x * a.x + x0.y * a.y + x0.z * a.z + x0.w * a.w
           + x1.x * a1.x + x1.y * a1.y + x1.z * a1.z + x1.w * a1.w;
        float4 b = wq4[lane], b1 = wq4[32 + lane];
        sq = x0.x * b.x + x0.y * b.y + x0.z * b.z + x0.w * b.w
           + x1.x * b1.x + x1.y * b1.y + x1.z * b1.z + x1.w * b1.w;
    }
    {
        __half2 h0 = __float22half2_rn(make_float2(x0.x, x0.y));
        __half2 h1 = __float22half2_rn(make_float2(x0.z, x0.w));
        __half2 h2 = __float22half2_rn(make_float2(x1.x, x1.y));
        __half2 h3 = __float22half2_rn(make_float2(x1.z, x1.w));
        uint2 p0 = make_uint2(*(unsigned*)&h0, *(unsigned*)&h1);
        uint2 p1 = make_uint2(*(unsigned*)&h2, *(unsigned*)&h3);
        *(uint2*)(g_inh + (size_t)warp * F + 4 * lane)       = p0;
        *(uint2*)(g_inh + (size_t)warp * F + 128 + 4 * lane) = p1;
    }
#pragma unroll
    for (int o = 16; o; o >>= 1) {
        sk += __shfl_xor_sync(FULLM, sk, o);
        sq += __shfl_xor_sync(FULLM, sq, o);
    }
    if (lane == 0) { g_K[warp] = sk; g_Q[warp] = sq; }
}

// ---------------- kernel 1b: QA table + W^T fp16 conversion + rf copy ----------------
__global__ void qa_kernel(const int* __restrict__ adj,
                          const float* __restrict__ W,
                          const int* __restrict__ rf,
                          float* __restrict__ out_rf) {
    int idx = blockIdx.x * blockDim.x + threadIdx.x;
    if (idx < F * F) {
        int n = idx >> 8, k = idx & (F - 1);
        g_Wth[idx] = __half_as_ushort(__float2half_rn(W[k * F + n]));
    }
    if (idx >= N_NODES * R) return;
    int id = adj[idx];
    g_QA[idx] = (id == N_NODES - 1) ? nan_f() : g_Q[id];
    if (out_rf) out_rf[idx] = (float)rf[idx];
}

// ---------------- kernel 2: attention softmax + fp16 aggregation (branchless inner loop) ----
__global__ void agg_kernel(const float* __restrict__ input,
                           const int* __restrict__ rf) {
    int gw = (blockIdx.x * blockDim.x + threadIdx.x) >> 5;
    int lane = threadIdx.x & 31;
    if (gw >= N_NODES) return;

    int rid = rf[gw * R + lane];
    float v = (rid == N_NODES - 1) ? -3.0e38f : g_K[gw] * g_Q[rid];
    float m = v;
#pragma unroll
    for (int o = 16; o; o >>= 1) m = fmaxf(m, __shfl_xor_sync(FULLM, m, o));
    float e = expf(v - m);   // masked: exactly 0.0f -> contributes nothing below
    float s = e;
#pragma unroll
    for (int o = 16; o; o >>= 1) s += __shfl_xor_sync(FULLM, s, o);
    float wgt = e / s;

    const float4* own = (const float4*)(input + (size_t)gw * F);
    float4 o0 = own[lane * 2];
    float4 o1 = own[lane * 2 + 1];
    float acc[8] = {o0.x, o0.y, o0.z, o0.w, o1.x, o1.y, o1.z, o1.w};

#pragma unroll 4
    for (int j = 0; j < R; j++) {
        float wj = __shfl_sync(FULLM, wgt, j);
        int id = __shfl_sync(FULLM, rid, j);
        uint4 h = *(const uint4*)(g_inh + (size_t)id * F + lane * 8);
        float2 f;
        f = __half22float2(*(__half2*)&h.x); acc[0] += wj * f.x; acc[1] += wj * f.y;
        f = __half22float2(*(__half2*)&h.y); acc[2] += wj * f.x; acc[3] += wj * f.y;
        f = __half22float2(*(__half2*)&h.z); acc[4] += wj * f.x; acc[5] += wj * f.y;
        f = __half22float2(*(__half2*)&h.w); acc[6] += wj * f.x; acc[7] += wj * f.y;
    }
    __half2 r0 = __float22half2_rn(make_float2(acc[0], acc[1]));
    __half2 r1 = __float22half2_rn(make_float2(acc[2], acc[3]));
    __half2 r2 = __float22half2_rn(make_float2(acc[4], acc[5]));
    __half2 r3 = __float22half2_rn(make_float2(acc[6], acc[7]));
    uint4 p = make_uint4(*(unsigned*)&r0, *(unsigned*)&r1, *(unsigned*)&r2, *(unsigned*)&r3);
    *(uint4*)(g_aggh + (size_t)gw * F + lane * 8) = p;
}

// ---------------- kernel 7: 2-hop expansion, exact stable top-32 of 1024 (R7-proven) ----------------
#define EWPB 8
#define VSTR 33
__global__ void expand_kernel(const int* __restrict__ rf,
                              const int* __restrict__ adj,
                              float* __restrict__ out_expand) {
    __shared__ unsigned V[EWPB][R * VSTR];
    int w = threadIdx.x >> 5;
    int lane = threadIdx.x & 31;
    int i = blockIdx.x * EWPB + w;
    if (i >= N_NODES) return;

    float key = g_K[i];
    int rfl = rf[i * R + lane];

    unsigned b0v = 0;
    int b0j = 0;
    const float4* qrow = (const float4*)(g_QA + (size_t)rfl * R);
    unsigned* Vrow = &V[w][lane * VSTR];
#pragma unroll
    for (int q = 0; q < 8; q++) {
        float4 x = qrow[q];
        float v0 = (x.x != x.x) ? -3.0e38f : key * x.x;
        float v1 = (x.y != x.y) ? -3.0e38f : key * x.y;
        float v2 = (x.z != x.z) ? -3.0e38f : key * x.z;
        float v3 = (x.w != x.w) ? -3.0e38f : key * x.w;
        unsigned m0 = fmap(v0), m1 = fmap(v1), m2 = fmap(v2), m3 = fmap(v3);
        Vrow[4 * q + 0] = m0;
        Vrow[4 * q + 1] = m1;
        Vrow[4 * q + 2] = m2;
        Vrow[4 * q + 3] = m3;
        if (m0 > b0v) { b0v = m0; b0j = 4 * q + 0; }
        if (m1 > b0v) { b0v = m1; b0j = 4 * q + 1; }
        if (m2 > b0v) { b0v = m2; b0j = 4 * q + 2; }
        if (m3 > b0v) { b0v = m3; b0j = 4 * q + 3; }
    }
    __syncwarp();

    int mwin = 0;
#pragma unroll 4
    for (int r = 0; r < R; r++) {
        unsigned mx = __reduce_max_sync(FULLM, b0v);
        unsigned cand = (b0v == mx) ? (unsigned)(lane * 32 + b0j) : FULLM;
        unsigned m = __reduce_min_sync(FULLM, cand);
        if (lane == r) mwin = (int)m;

        int winL = m >> 5, jwin = m & 31;
        unsigned x = V[w][winL * VSTR + lane];
        if (lane == jwin) {
            x = 0;
            V[w][winL * VSTR + jwin] = 0;
        }
        unsigned mx2 = __reduce_max_sync(FULLM, x);
        unsigned jc = (x == mx2) ? (unsigned)lane : FULLM;
        unsigned j2 = __reduce_min_sync(FULLM, jc);
        if (lane == winL) { b0v = mx2; b0j = (int)j2; }
        __syncwarp();
    }

    int k = mwin >> 5, j = mwin & 31;
    int rk = __shfl_sync(FULLM, rfl, k);
    out_expand[(size_t)i * R + lane] = (float)adj[(size_t)rk * R + j];
}

// ---------------- kernel 3: fp16 MMA GEMM (cp.async 2-stage, K-chunk 64) + fused col sums ----
#define GBM 128
#define GBN 128
#define GKC 64
#define ASTR 36                    // stride in half2 units
#define TSZ (GBM * ASTR)           // half2 per tile = 4608
#define STG (2 * TSZ)              // half2 per stage (A + B)
#define GEMM_SMEM (2 * STG * 4)    // bytes, 2 stages = 73728
#define NKT (F / GKC)              // 4

__global__ void __launch_bounds__(256, 2) gemm_kernel() {
    extern __shared__ unsigned sm[];           // half2 units
    unsigned smb = (unsigned)__cvta_generic_to_shared(sm);
    int bm = blockIdx.x * GBM;
    int bn = blockIdx.y * GBN;
    int t = threadIdx.x;
    int lane = t & 31, warp = t >> 5;
    int warp_m = warp >> 1, warp_n = warp & 1;
    int g = lane >> 2, tg = lane & 3;
    int m0 = warp_m * 32, n0 = warp_n * 64;

    int arow = t >> 1;
    int ah = (t & 1) * 32;
    int gr = bm + arow;
    int asz = (gr < N_NODES) ? 16 : 0;
    const unsigned short* asrc = g_aggh + (size_t)(gr < N_NODES ? gr : 0) * F + ah;
    const unsigned short* bsrc = g_Wth + (size_t)(bn + arow) * F + ah;

    float acc[2][8][4];
#pragma unroll
    for (int mt = 0; mt < 2; mt++)
#pragma unroll
        for (int nt = 0; nt < 8; nt++)
#pragma unroll
            for (int c = 0; c < 4; c++) acc[mt][nt][c] = 0.0f;

    auto issue = [&](int stage, int kt) {
        unsigned ab = smb + (stage * STG + arow * ASTR + (ah >> 1)) * 4;
        const unsigned short* as = asrc + kt;
#pragma unroll
        for (int q = 0; q < 4; q++) cp16(ab + q * 16, as + q * 8, asz);
        unsigned bb = smb + (stage * STG + TSZ + arow * ASTR + (ah >> 1)) * 4;
        const unsigned short* bs = bsrc + kt;
#pragma unroll
        for (int q = 0; q < 4; q++) cp16(bb + q * 16, bs + q * 8, 16);
        asm volatile("cp.async.commit_group;");
    };

    issue(0, 0);

    for (int s = 0; s < NKT; s++) {
        if (s + 1 < NKT) {
            issue((s + 1) & 1, (s + 1) * GKC);
            asm volatile("cp.async.wait_group 1;");
        } else {
            asm volatile("cp.async.wait_group 0;");
        }
        __syncthreads();

        const unsigned* As = sm + (s & 1) * STG;
        const unsigned* Bs = sm + (s & 1) * STG + TSZ;
#pragma unroll
        for (int kk = 0; kk < 4; kk++) {
            int k2 = kk * 8;
            unsigned af[2][4];
#pragma unroll
            for (int mt = 0; mt < 2; mt++) {
                int r0 = m0 + mt * 16 + g;
                af[mt][0] = As[r0 * ASTR + k2 + tg];
                af[mt][1] = As[(r0 + 8) * ASTR + k2 + tg];
                af[mt][2] = As[r0 * ASTR + k2 + tg + 4];
                af[mt][3] = As[(r0 + 8) * ASTR + k2 + tg + 4];
            }
            unsigned bf[8][2];
#pragma unroll
            for (int nt = 0; nt < 8; nt++) {
                int nr = n0 + nt * 8 + g;
                bf[nt][0] = Bs[nr * ASTR + k2 + tg];
                bf[nt][1] = Bs[nr * ASTR + k2 + tg + 4];
            }
#pragma unroll
            for (int mt = 0; mt < 2; mt++)
#pragma unroll
                for (int nt = 0; nt < 8; nt++) {
                    asm volatile(
                        "mma.sync.aligned.m16n8k16.row.col.f32.f16.f16.f32 "
                        "{%0,%1,%2,%3}, {%4,%5,%6,%7}, {%8,%9}, {%0,%1,%2,%3};"
                        : "+f"(acc[mt][nt][0]), "+f"(acc[mt][nt][1]),
                          "+f"(acc[mt][nt][2]), "+f"(acc[mt][nt][3])
                        : "r"(af[mt][0]), "r"(af[mt][1]), "r"(af[mt][2]), "r"(af[mt][3]),
                          "r"(bf[nt][0]), "r"(bf[nt][1]));
                }
        }
        __syncthreads();
    }

#pragma unroll
    for (int mt = 0; mt < 2; mt++) {
        int row0 = bm + m0 + mt * 16 + g;
        int row1 = row0 + 8;
#pragma unroll
        for (int nt = 0; nt < 8; nt++) {
            int col = bn + n0 + nt * 8 + 2 * tg;
            if (row0 < N_NODES)
                *(float2*)(g_fin + (size_t)row0 * F + col) =
                    make_float2(acc[mt][nt][0], acc[mt][nt][1]);
            if (row1 < N_NODES)
                *(float2*)(g_fin + (size_t)row1 * F + col) =
                    make_float2(acc[mt][nt][2], acc[mt][nt][3]);
        }
    }
#pragma unroll
    for (int nt = 0; nt < 8; nt++) {
        float s0 = acc[0][nt][0] + acc[0][nt][2] + acc[1][nt][0] + acc[1][nt][2];
        float s1 = acc[0][nt][1] + acc[0][nt][3] + acc[1][nt][1] + acc[1][nt][3];
        float q0 = acc[0][nt][0] * acc[0][nt][0] + acc[0][nt][2] * acc[0][nt][2]
                 + acc[1][nt][0] * acc[1][nt][0] + acc[1][nt][2] * acc[1][nt][2];
        float q1 = acc[0][nt][1] * acc[0][nt][1] + acc[0][nt][3] * acc[0][nt][3]
                 + acc[1][nt][1] * acc[1][nt][1] + acc[1][nt][3] * acc[1][nt][3];
#pragma unroll
        for (int o = 4; o <= 16; o <<= 1) {
            s0 += __shfl_xor_sync(FULLM, s0, o);
            s1 += __shfl_xor_sync(FULLM, s1, o);
            q0 += __shfl_xor_sync(FULLM, q0, o);
            q1 += __shfl_xor_sync(FULLM, q1, o);
        }
        if (lane < 4) {
            int col = bn + n0 + nt * 8 + 2 * tg;
            atomicAdd(&g_colsum[col], s0);
            atomicAdd(&g_colsum[col + 1], s1);
            atomicAdd(&g_colsumsq[col], q0);
            atomicAdd(&g_colsumsq[col + 1], q1);
        }
    }
}

// ---------------- kernel 5: batchnorm + relu -> out (float4 per thread, R12-proven) ----------
__global__ void bn_kernel(const float* __restrict__ gamma,
                          const float* __restrict__ beta,
                          float* __restrict__ out) {
    int idx4 = blockIdx.x * blockDim.x + threadIdx.x;
    if (idx4 >= N_NODES * F / 4) return;
    int c = (idx4 * 4) & (F - 1);
    const float invn = 1.0f / (float)N_NODES;
    float4 x = *(const float4*)(g_fin + (size_t)idx4 * 4);
    float4 y;
    {
        float mean = g_colsum[c + 0] * invn;
        float var = g_colsumsq[c + 0] * invn - mean * mean;
        y.x = fmaxf(gamma[c + 0] * (x.x - mean) * rsqrtf(var + BN_EPS) + beta[c + 0], 0.0f);
    }
    {
        float mean = g_colsum[c + 1] * invn;
        float var = g_colsumsq[c + 1] * invn - mean * mean;
        y.y = fmaxf(gamma[c + 1] * (x.y - mean) * rsqrtf(var + BN_EPS) + beta[c + 1], 0.0f);
    }
    {
        float mean = g_colsum[c + 2] * invn;
        float var = g_colsumsq[c + 2] * invn - mean * mean;
        y.z = fmaxf(gamma[c + 2] * (x.z - mean) * rsqrtf(var + BN_EPS) + beta[c + 2], 0.0f);
    }
    {
        float mean = g_colsum[c + 3] * invn;
        float var = g_colsumsq[c + 3] * invn - mean * mean;
        y.w = fmaxf(gamma[c + 3] * (x.w - mean) * rsqrtf(var + BN_EPS) + beta[c + 3], 0.0f);
    }
    *(float4*)(out + (size_t)idx4 * 4) = y;
}

// ---------------- launch: parallel graph — qa+expand branch hides under agg+gemm ----------------
extern "C" void kernel_launch(void* const* d_in, const int* in_sizes, int n_in,
                              void* d_out, int out_size) {
    const float* input = (const float*)d_in[0];
    const int*   rf    = (const int*)d_in[1];
    const int*   adj   = (const int*)d_in[2];
    const float* W     = (const float*)d_in[3];
    const float* Wk    = (const float*)d_in[4];
    const float* Wq    = (const float*)d_in[5];
    const float* gamma = (const float*)d_in[6];
    const float* beta  = (const float*)d_in[7];
    float* out = (float*)d_out;

    static bool attr_done = false;
    if (!attr_done) {
        cudaFuncSetAttribute(gemm_kernel,
                             cudaFuncAttributeMaxDynamicSharedMemorySize, GEMM_SMEM);
        attr_done = true;
    }

    bool full_out = (out_size >= N_NODES * F + 2 * N_NODES * R);
    float* out_rf = full_out ? (out + N_NODES * F) : nullptr;
    float* out_ex = full_out ? (out + N_NODES * F + N_NODES * R) : nullptr;
    bool fork = g_gs.ok;

    dim3 gg((N_NODES + GBM - 1) / GBM, F / GBN);

    kq_kernel<<<(N_NODES * 32 + 255) / 256, 256>>>(input, Wk, Wq);          // 0

    if (fork) {
        // side branch: qa -> expand, overlapped with agg -> gemm on the main stream
        cudaEventRecord(g_gs.e1, 0);
        cudaStreamWaitEvent(g_gs.s2, g_gs.e1, 0);

        agg_kernel<<<(N_NODES * 32 + 255) / 256, 256>>>(input, rf);         // 1 (main)
        qa_kernel<<<(N_NODES * R + 255) / 256, 256, 0, g_gs.s2>>>(
            adj, W, rf, out_rf);                                            // 2 (s2)
        cudaEventRecord(g_gs.eqa, g_gs.s2);

        cudaStreamWaitEvent(0, g_gs.eqa, 0);   // gemm needs g_Wth
        gemm_kernel<<<gg, 256, GEMM_SMEM>>>();                              // 3 (main, profiled)

        if (full_out) {
            expand_kernel<<<(N_NODES + EWPB - 1) / EWPB, EWPB * 32, 0, g_gs.s2>>>(
                rf, adj, out_ex);                                           // 4 (s2)
        }
        cudaEventRecord(g_gs.e2, g_gs.s2);
        cudaStreamWaitEvent(0, g_gs.e2, 0);    // join before final output pass
    } else {
        // degraded serial path
        qa_kernel<<<(N_NODES * R + 255) / 256, 256>>>(adj, W, rf, out_rf);
        agg_kernel<<<(N_NODES * 32 + 255) / 256, 256>>>(input, rf);
        if (full_out)
            expand_kernel<<<(N_NODES + EWPB - 1) / EWPB, EWPB * 32>>>(rf, adj, out_ex);
        gemm_kernel<<<gg, 256, GEMM_SMEM>>>();
    }

    bn_kernel<<<(N_NODES * F / 4 + 255) / 256, 256>>>(gamma, beta, out);    // 5
}

// round 16
// speedup vs baseline: 1.1943x; 1.0124x over previous
#include <cuda_runtime.h>
#include <cuda_fp16.h>

#define N_NODES 20000
#define F 256
#define R 32
#define NEI2 (R * R)
#define BN_EPS 1e-5f
#define FULLM 0xffffffffu

// ---------------- scratch (no allocations allowed) ----------------
__device__ float g_K[N_NODES];
__device__ float g_Q[N_NODES];
__device__ __align__(16) float g_QA[(size_t)N_NODES * R];    // Q[adj[c][j]] (NaN if masked)
__device__ __align__(16) unsigned short g_inh[(size_t)N_NODES * F];   // fp16 input copy
__device__ __align__(16) unsigned short g_aggh[(size_t)N_NODES * F];  // aggregated rows, fp16
__device__ __align__(16) unsigned short g_Wth[F * F];                 // W^T (n-major), fp16
__device__ float g_fin[(size_t)N_NODES * F];   // pre-BN final_h
__device__ float g_colsum[F];
__device__ float g_colsumsq[F];

__device__ __forceinline__ float nan_f()  { return __int_as_float(0x7fffffffu); }

// order-preserving float -> uint map (never 0 for non-NaN input)
__device__ __forceinline__ unsigned fmap(float v) {
    unsigned b = __float_as_uint(v);
    return (b & 0x80000000u) ? ~b : (b | 0x80000000u);
}

__device__ __forceinline__ void cp16(unsigned dst, const void* src, int sz) {
    asm volatile("cp.async.cg.shared.global [%0], [%1], 16, %2;"
                 :: "r"(dst), "l"(src), "r"(sz));
}

// ---------------- side stream + fork/join events (created pre-capture, no device mem APIs) ----
struct GraphStreams {
    cudaStream_t s2 = 0;
    cudaEvent_t e1 = 0, eqa = 0, e2 = 0;
    bool ok = false;
    GraphStreams() {
        ok = (cudaStreamCreateWithFlags(&s2, cudaStreamNonBlocking) == cudaSuccess)
          && (cudaEventCreateWithFlags(&e1, cudaEventDisableTiming) == cudaSuccess)
          && (cudaEventCreateWithFlags(&eqa, cudaEventDisableTiming) == cudaSuccess)
          && (cudaEventCreateWithFlags(&e2, cudaEventDisableTiming) == cudaSuccess);
        if (!ok) s2 = 0;
    }
};
static GraphStreams g_gs;

// ---------------- kernel 1: Key/Query scalars + fp16 copy + BN-acc zeroing ----------------
__global__ void kq_kernel(const float* __restrict__ input,
                          const float* __restrict__ Wk,
                          const float* __restrict__ Wq) {
    if (blockIdx.x == 0) {
        int t = threadIdx.x;
        if (t < F) { g_colsum[t] = 0.0f; g_colsumsq[t] = 0.0f; }
    }
    int warp = (blockIdx.x * blockDim.x + threadIdx.x) >> 5;
    int lane = threadIdx.x & 31;
    if (warp >= N_NODES) return;
    const float4* row = (const float4*)(input + (size_t)warp * F);
    const float4* wk4 = (const float4*)Wk;
    const float4* wq4 = (const float4*)Wq;
    float4 x0 = row[lane];
    float4 x1 = row[32 + lane];
    float sk, sq;
    {
        float4 a = wk4[lane], a1 = wk4[32 + lane];
        sk = x0.x * a.x + x0.y * a.y + x0.z * a.z + x0.w * a.w
           + x1.x * a1.x + x1.y * a1.y + x1.z * a1.z + x1.w * a1.w;
        float4 b = wq4[lane], b1 = wq4[32 + lane];
        sq = x0.x * b.x + x0.y * b.y + x0.z * b.z + x0.w * b.w
           + x1.x * b1.x + x1.y * b1.y + x1.z * b1.z + x1.w * b1.w;
    }
    {
        __half2 h0 = __float22half2_rn(make_float2(x0.x, x0.y));
        __half2 h1 = __float22half2_rn(make_float2(x0.z, x0.w));
        __half2 h2 = __float22half2_rn(make_float2(x1.x, x1.y));
        __half2 h3 = __float22half2_rn(make_float2(x1.z, x1.w));
        uint2 p0 = make_uint2(*(unsigned*)&h0, *(unsigned*)&h1);
        uint2 p1 = make_uint2(*(unsigned*)&h2, *(unsigned*)&h3);
        *(uint2*)(g_inh + (size_t)warp * F + 4 * lane)       = p0;
        *(uint2*)(g_inh + (size_t)warp * F + 128 + 4 * lane) = p1;
    }
#pragma unroll
    for (int o = 16; o; o >>= 1) {
        sk += __shfl_xor_sync(FULLM, sk, o);
        sq += __shfl_xor_sync(FULLM, sq, o);
    }
    if (lane == 0) { g_K[warp] = sk; g_Q[warp] = sq; }
}

// ---------------- kernel 1b: QA table + W^T fp16 conversion + rf copy ----------------
__global__ void qa_kernel(const int* __restrict__ adj,
                          const float* __restrict__ W,
                          const int* __restrict__ rf,
                          float* __restrict__ out_rf) {
    int idx = blockIdx.x * blockDim.x + threadIdx.x;
    if (idx < F * F) {
        int n = idx >> 8, k = idx & (F - 1);
        g_Wth[idx] = __half_as_ushort(__float2half_rn(W[k * F + n]));
    }
    if (idx >= N_NODES * R) return;
    int id = adj[idx];
    g_QA[idx] = (id == N_NODES - 1) ? nan_f() : g_Q[id];
    if (out_rf) out_rf[idx] = (float)rf[idx];
}

// ---------------- kernel 2: attention softmax + fp16 aggregation (branchless inner loop) ----
__global__ void agg_kernel(const float* __restrict__ input,
                           const int* __restrict__ rf) {
    int gw = (blockIdx.x * blockDim.x + threadIdx.x) >> 5;
    int lane = threadIdx.x & 31;
    if (gw >= N_NODES) return;

    int rid = rf[gw * R + lane];
    float v = (rid == N_NODES - 1) ? -3.0e38f : g_K[gw] * g_Q[rid];
    float m = v;
#pragma unroll
    for (int o = 16; o; o >>= 1) m = fmaxf(m, __shfl_xor_sync(FULLM, m, o));
    float e = expf(v - m);   // masked: exactly 0.0f -> contributes nothing below
    float s = e;
#pragma unroll
    for (int o = 16; o; o >>= 1) s += __shfl_xor_sync(FULLM, s, o);
    float wgt = e / s;

    const float4* own = (const float4*)(input + (size_t)gw * F);
    float4 o0 = own[lane * 2];
    float4 o1 = own[lane * 2 + 1];
    float acc[8] = {o0.x, o0.y, o0.z, o0.w, o1.x, o1.y, o1.z, o1.w};

#pragma unroll 4
    for (int j = 0; j < R; j++) {
        float wj = __shfl_sync(FULLM, wgt, j);
        int id = __shfl_sync(FULLM, rid, j);
        uint4 h = *(const uint4*)(g_inh + (size_t)id * F + lane * 8);
        float2 f;
        f = __half22float2(*(__half2*)&h.x); acc[0] += wj * f.x; acc[1] += wj * f.y;
        f = __half22float2(*(__half2*)&h.y); acc[2] += wj * f.x; acc[3] += wj * f.y;
        f = __half22float2(*(__half2*)&h.z); acc[4] += wj * f.x; acc[5] += wj * f.y;
        f = __half22float2(*(__half2*)&h.w); acc[6] += wj * f.x; acc[7] += wj * f.y;
    }
    __half2 r0 = __float22half2_rn(make_float2(acc[0], acc[1]));
    __half2 r1 = __float22half2_rn(make_float2(acc[2], acc[3]));
    __half2 r2 = __float22half2_rn(make_float2(acc[4], acc[5]));
    __half2 r3 = __float22half2_rn(make_float2(acc[6], acc[7]));
    uint4 p = make_uint4(*(unsigned*)&r0, *(unsigned*)&r1, *(unsigned*)&r2, *(unsigned*)&r3);
    *(uint4*)(g_aggh + (size_t)gw * F + lane * 8) = p;
}

// ---------------- kernel 7: 2-hop expansion, exact stable top-32 of 1024 (R7-proven) ----------------
#define EWPB 8
#define VSTR 33
__global__ void expand_kernel(const int* __restrict__ rf,
                              const int* __restrict__ adj,
                              float* __restrict__ out_expand) {
    __shared__ unsigned V[EWPB][R * VSTR];
    int w = threadIdx.x >> 5;
    int lane = threadIdx.x & 31;
    int i = blockIdx.x * EWPB + w;
    if (i >= N_NODES) return;

    float key = g_K[i];
    int rfl = rf[i * R + lane];

    unsigned b0v = 0;
    int b0j = 0;
    const float4* qrow = (const float4*)(g_QA + (size_t)rfl * R);
    unsigned* Vrow = &V[w][lane * VSTR];
#pragma unroll
    for (int q = 0; q < 8; q++) {
        float4 x = qrow[q];
        float v0 = (x.x != x.x) ? -3.0e38f : key * x.x;
        float v1 = (x.y != x.y) ? -3.0e38f : key * x.y;
        float v2 = (x.z != x.z) ? -3.0e38f : key * x.z;
        float v3 = (x.w != x.w) ? -3.0e38f : key * x.w;
        unsigned m0 = fmap(v0), m1 = fmap(v1), m2 = fmap(v2), m3 = fmap(v3);
        Vrow[4 * q + 0] = m0;
        Vrow[4 * q + 1] = m1;
        Vrow[4 * q + 2] = m2;
        Vrow[4 * q + 3] = m3;
        if (m0 > b0v) { b0v = m0; b0j = 4 * q + 0; }
        if (m1 > b0v) { b0v = m1; b0j = 4 * q + 1; }
        if (m2 > b0v) { b0v = m2; b0j = 4 * q + 2; }
        if (m3 > b0v) { b0v = m3; b0j = 4 * q + 3; }
    }
    __syncwarp();

    int mwin = 0;
#pragma unroll 4
    for (int r = 0; r < R; r++) {
        unsigned mx = __reduce_max_sync(FULLM, b0v);
        unsigned cand = (b0v == mx) ? (unsigned)(lane * 32 + b0j) : FULLM;
        unsigned m = __reduce_min_sync(FULLM, cand);
        if (lane == r) mwin = (int)m;

        int winL = m >> 5, jwin = m & 31;
        unsigned x = V[w][winL * VSTR + lane];
        if (lane == jwin) {
            x = 0;
            V[w][winL * VSTR + jwin] = 0;
        }
        unsigned mx2 = __reduce_max_sync(FULLM, x);
        unsigned jc = (x == mx2) ? (unsigned)lane : FULLM;
        unsigned j2 = __reduce_min_sync(FULLM, jc);
        if (lane == winL) { b0v = mx2; b0j = (int)j2; }
        __syncwarp();
    }

    int k = mwin >> 5, j = mwin & 31;
    int rk = __shfl_sync(FULLM, rfl, k);
    out_expand[(size_t)i * R + lane] = (float)adj[(size_t)rk * R + j];
}

// ---------------- kernel 3: fp16 MMA GEMM, 4-stage cp.async pipeline (GKC=32) ----------------
// Block 128x128, 8 warps (4x2), warp tile 32x64 = 2x8 m16n8k16.
// Stage: A 128x16 half2 + B 128x16 half2, stride 20 half2 (conflict-free: {g*20+tg} mod 32
// covers all banks). 8 K-chunks, 3 cp.async groups in flight -> loads stay ahead of compute.
#define GBM 128
#define GBN 128
#define GKC 32
#define ASTR 20                    // stride in half2 units
#define TSZ (GBM * ASTR)           // half2 per tile = 2560
#define STG (2 * TSZ)              // half2 per stage (A + B) = 5120
#define NSTG 4
#define GEMM_SMEM (NSTG * STG * 4) // 81920 bytes
#define NKT (F / GKC)              // 8

__global__ void __launch_bounds__(256, 2) gemm_kernel() {
    extern __shared__ unsigned sm[];           // half2 units
    unsigned smb = (unsigned)__cvta_generic_to_shared(sm);
    int bm = blockIdx.x * GBM;
    int bn = blockIdx.y * GBN;
    int t = threadIdx.x;
    int lane = t & 31, warp = t >> 5;
    int warp_m = warp >> 1, warp_n = warp & 1;
    int g = lane >> 2, tg = lane & 3;
    int m0 = warp_m * 32, n0 = warp_n * 64;

    int arow = t >> 1;                         // 0..127
    int ah = (t & 1) * 16;                     // half offset within 32-half row chunk
    int gr = bm + arow;
    int asz = (gr < N_NODES) ? 16 : 0;
    const unsigned short* asrc = g_aggh + (size_t)(gr < N_NODES ? gr : 0) * F + ah;
    const unsigned short* bsrc = g_Wth + (size_t)(bn + arow) * F + ah;

    float acc[2][8][4];
#pragma unroll
    for (int mt = 0; mt < 2; mt++)
#pragma unroll
        for (int nt = 0; nt < 8; nt++)
#pragma unroll
            for (int c = 0; c < 4; c++) acc[mt][nt][c] = 0.0f;

    // copy one stage: A rows [bm..+127] k [kt..kt+31]; B n-rows [bn..+127] same k
    auto issue = [&](int stage, int kt) {
        unsigned ab = smb + (stage * STG + arow * ASTR + (ah >> 1)) * 4;
        const unsigned short* as = asrc + kt;
#pragma unroll
        for (int q = 0; q < 2; q++) cp16(ab + q * 16, as + q * 8, asz);
        unsigned bb = smb + (stage * STG + TSZ + arow * ASTR + (ah >> 1)) * 4;
        const unsigned short* bs = bsrc + kt;
#pragma unroll
        for (int q = 0; q < 2; q++) cp16(bb + q * 16, bs + q * 8, 16);
        asm volatile("cp.async.commit_group;");
    };

    issue(0, 0);
    issue(1, GKC);
    issue(2, 2 * GKC);

    for (int s = 0; s < NKT; s++) {
        if (s + 3 < NKT) {
            issue((s + 3) & (NSTG - 1), (s + 3) * GKC);
            asm volatile("cp.async.wait_group 3;");
        } else {
            int rem = NKT - 1 - s;
            if (rem == 2)      asm volatile("cp.async.wait_group 2;");
            else if (rem == 1) asm volatile("cp.async.wait_group 1;");
            else               asm volatile("cp.async.wait_group 0;");
        }
        __syncthreads();

        const unsigned* As = sm + (s & (NSTG - 1)) * STG;
        const unsigned* Bs = sm + (s & (NSTG - 1)) * STG + TSZ;
#pragma unroll
        for (int kk = 0; kk < 2; kk++) {       // 2 k-steps of 16 within the 32-chunk
            int k2 = kk * 8;
            unsigned af[2][4];
#pragma unroll
            for (int mt = 0; mt < 2; mt++) {
                int r0 = m0 + mt * 16 + g;
                af[mt][0] = As[r0 * ASTR + k2 + tg];
                af[mt][1] = As[(r0 + 8) * ASTR + k2 + tg];
                af[mt][2] = As[r0 * ASTR + k2 + tg + 4];
                af[mt][3] = As[(r0 + 8) * ASTR + k2 + tg + 4];
            }
            unsigned bf[8][2];
#pragma unroll
            for (int nt = 0; nt < 8; nt++) {
                int nr = n0 + nt * 8 + g;
                bf[nt][0] = Bs[nr * ASTR + k2 + tg];
                bf[nt][1] = Bs[nr * ASTR + k2 + tg + 4];
            }
#pragma unroll
            for (int mt = 0; mt < 2; mt++)
#pragma unroll
                for (int nt = 0; nt < 8; nt++) {
                    asm volatile(
                        "mma.sync.aligned.m16n8k16.row.col.f32.f16.f16.f32 "
                        "{%0,%1,%2,%3}, {%4,%5,%6,%7}, {%8,%9}, {%0,%1,%2,%3};"
                        : "+f"(acc[mt][nt][0]), "+f"(acc[mt][nt][1]),
                          "+f"(acc[mt][nt][2]), "+f"(acc[mt][nt][3])
                        : "r"(af[mt][0]), "r"(af[mt][1]), "r"(af[mt][2]), "r"(af[mt][3]),
                          "r"(bf[nt][0]), "r"(bf[nt][1]));
                }
        }
        __syncthreads();
    }

    // store C + fused column sum / sum-of-squares (OOB rows are exact zeros)
#pragma unroll
    for (int mt = 0; mt < 2; mt++) {
        int row0 = bm + m0 + mt * 16 + g;
        int row1 = row0 + 8;
#pragma unroll
        for (int nt = 0; nt < 8; nt++) {
            int col = bn + n0 + nt * 8 + 2 * tg;
            if (row0 < N_NODES)
                *(float2*)(g_fin + (size_t)row0 * F + col) =
                    make_float2(acc[mt][nt][0], acc[mt][nt][1]);
            if (row1 < N_NODES)
                *(float2*)(g_fin + (size_t)row1 * F + col) =
                    make_float2(acc[mt][nt][2], acc[mt][nt][3]);
        }
    }
#pragma unroll
    for (int nt = 0; nt < 8; nt++) {
        float s0 = acc[0][nt][0] + acc[0][nt][2] + acc[1][nt][0] + acc[1][nt][2];
        float s1 = acc[0][nt][1] + acc[0][nt][3] + acc[1][nt][1] + acc[1][nt][3];
        float q0 = acc[0][nt][0] * acc[0][nt][0] + acc[0][nt][2] * acc[0][nt][2]
                 + acc[1][nt][0] * acc[1][nt][0] + acc[1][nt][2] * acc[1][nt][2];
        float q1 = acc[0][nt][1] * acc[0][nt][1] + acc[0][nt][3] * acc[0][nt][3]
                 + acc[1][nt][1] * acc[1][nt][1] + acc[1][nt][3] * acc[1][nt][3];
#pragma unroll
        for (int o = 4; o <= 16; o <<= 1) {
            s0 += __shfl_xor_sync(FULLM, s0, o);
            s1 += __shfl_xor_sync(FULLM, s1, o);
            q0 += __shfl_xor_sync(FULLM, q0, o);
            q1 += __shfl_xor_sync(FULLM, q1, o);
        }
        if (lane < 4) {
            int col = bn + n0 + nt * 8 + 2 * tg;
            atomicAdd(&g_colsum[col], s0);
            atomicAdd(&g_colsum[col + 1], s1);
            atomicAdd(&g_colsumsq[col], q0);
            atomicAdd(&g_colsumsq[col + 1], q1);
        }
    }
}

// ---------------- kernel 5: batchnorm + relu -> out (float4 per thread, R12-proven) ----------
__global__ void bn_kernel(const float* __restrict__ gamma,
                          const float* __restrict__ beta,
                          float* __restrict__ out) {
    int idx4 = blockIdx.x * blockDim.x + threadIdx.x;
    if (idx4 >= N_NODES * F / 4) return;
    int c = (idx4 * 4) & (F - 1);
    const float invn = 1.0f / (float)N_NODES;
    float4 x = *(const float4*)(g_fin + (size_t)idx4 * 4);
    float4 y;
    {
        float mean = g_colsum[c + 0] * invn;
        float var = g_colsumsq[c + 0] * invn - mean * mean;
        y.x = fmaxf(gamma[c + 0] * (x.x - mean) * rsqrtf(var + BN_EPS) + beta[c + 0], 0.0f);
    }
    {
        float mean = g_colsum[c + 1] * invn;
        float var = g_colsumsq[c + 1] * invn - mean * mean;
        y.y = fmaxf(gamma[c + 1] * (x.y - mean) * rsqrtf(var + BN_EPS) + beta[c + 1], 0.0f);
    }
    {
        float mean = g_colsum[c + 2] * invn;
        float var = g_colsumsq[c + 2] * invn - mean * mean;
        y.z = fmaxf(gamma[c + 2] * (x.z - mean) * rsqrtf(var + BN_EPS) + beta[c + 2], 0.0f);
    }
    {
        float mean = g_colsum[c + 3] * invn;
        float var = g_colsumsq[c + 3] * invn - mean * mean;
        y.w = fmaxf(gamma[c + 3] * (x.w - mean) * rsqrtf(var + BN_EPS) + beta[c + 3], 0.0f);
    }
    *(float4*)(out + (size_t)idx4 * 4) = y;
}

// ---------------- launch: parallel graph — qa+expand branch hides under agg+gemm ----------------
extern "C" void kernel_launch(void* const* d_in, const int* in_sizes, int n_in,
                              void* d_out, int out_size) {
    const float* input = (const float*)d_in[0];
    const int*   rf    = (const int*)d_in[1];
    const int*   adj   = (const int*)d_in[2];
    const float* W     = (const float*)d_in[3];
    const float* Wk    = (const float*)d_in[4];
    const float* Wq    = (const float*)d_in[5];
    const float* gamma = (const float*)d_in[6];
    const float* beta  = (const float*)d_in[7];
    float* out = (float*)d_out;

    static bool attr_done = false;
    if (!attr_done) {
        cudaFuncSetAttribute(gemm_kernel,
                             cudaFuncAttributeMaxDynamicSharedMemorySize, GEMM_SMEM);
        attr_done = true;
    }

    bool full_out = (out_size >= N_NODES * F + 2 * N_NODES * R);
    float* out_rf = full_out ? (out + N_NODES * F) : nullptr;
    float* out_ex = full_out ? (out + N_NODES * F + N_NODES * R) : nullptr;
    bool fork = g_gs.ok;

    dim3 gg((N_NODES + GBM - 1) / GBM, F / GBN);

    kq_kernel<<<(N_NODES * 32 + 255) / 256, 256>>>(input, Wk, Wq);          // 0

    if (fork) {
        // side branch: qa -> expand, overlapped with agg -> gemm on the main stream
        cudaEventRecord(g_gs.e1, 0);
        cudaStreamWaitEvent(g_gs.s2, g_gs.e1, 0);

        agg_kernel<<<(N_NODES * 32 + 255) / 256, 256>>>(input, rf);         // 1 (main)
        qa_kernel<<<(N_NODES * R + 255) / 256, 256, 0, g_gs.s2>>>(
            adj, W, rf, out_rf);                                            // 2 (s2)
        cudaEventRecord(g_gs.eqa, g_gs.s2);

        cudaStreamWaitEvent(0, g_gs.eqa, 0);   // gemm needs g_Wth
        gemm_kernel<<<gg, 256, GEMM_SMEM>>>();                              // 3 (main, profiled)

        if (full_out) {
            expand_kernel<<<(N_NODES + EWPB - 1) / EWPB, EWPB * 32, 0, g_gs.s2>>>(
                rf, adj, out_ex);                                           // 4 (s2)
        }
        cudaEventRecord(g_gs.e2, g_gs.s2);
        cudaStreamWaitEvent(0, g_gs.e2, 0);    // join before final output pass
    } else {
        // degraded serial path
        qa_kernel<<<(N_NODES * R + 255) / 256, 256>>>(adj, W, rf, out_rf);
        agg_kernel<<<(N_NODES * 32 + 255) / 256, 256>>>(input, rf);
        if (full_out)
            expand_kernel<<<(N_NODES + EWPB - 1) / EWPB, EWPB * 32>>>(rf, adj, out_ex);
        gemm_kernel<<<gg, 256, GEMM_SMEM>>>();
    }

    bn_kernel<<<(N_NODES * F / 4 + 255) / 256, 256>>>(gamma, beta, out);    // 5
}